// round 7
// baseline (speedup 1.0000x reference)
#include <cuda_runtime.h>
#include <cstdint>
#include <cstddef>

// Problem constants
#define NB   4
#define TLEN 2048
#define DMODEL 1024
#define NH   16
#define DK   64
#define MROWS (NB * TLEN)        // 8192
#define QKVCOLS (3 * DMODEL)     // 3072

// Q pre-scale: 1/sqrt(64) * log2(e)  (softmax runs in exp2 domain)
#define QSCALE 0.1803368801111204f

// Scratch (device globals)
__device__ float g_qkv[(size_t)MROWS * QKVCOLS];        // 100.7 MB (tf32, Q pre-scaled)
__device__ float g_att[(size_t)MROWS * DMODEL];         // 33.6 MB  (tf32)
__device__ float g_zr[(size_t)MROWS * DMODEL];          // 33.6 MB  (z, tf32-rounded)
__device__ float g_vt[(size_t)NB * NH * DK * TLEN];     // 33.6 MB  (V^T per (n,h): [d][t])
__device__ float g_wtqkv[(size_t)QKVCOLS * DMODEL];     // 12.6 MB
__device__ float g_wtout[(size_t)DMODEL * DMODEL];      // 4.2 MB

__device__ __forceinline__ float tf32r(float x) {
    uint32_t u;
    asm("cvt.rna.tf32.f32 %0, %1;" : "=r"(u) : "f"(x));
    return __uint_as_float(u);
}

__device__ __forceinline__ float ex2(float x) {
    float y;
    asm("ex2.approx.f32 %0, %1;" : "=f"(y) : "f"(x));
    return y;
}

__device__ __forceinline__ uint32_t smem_u32(const void* p) {
    uint32_t a;
    asm("{ .reg .u64 t; cvta.to.shared.u64 t, %1; cvt.u32.u64 %0, t; }"
        : "=r"(a) : "l"(p));
    return a;
}

__device__ __forceinline__ void cp16(uint32_t dst, const void* src) {
    asm volatile("cp.async.cg.shared.global [%0], [%1], 16;"
                 :: "r"(dst), "l"(src));
}
#define CP_COMMIT() asm volatile("cp.async.commit_group;" ::: "memory")
#define CP_WAIT0()  asm volatile("cp.async.wait_group 0;" ::: "memory")
#define CP_WAIT1()  asm volatile("cp.async.wait_group 1;" ::: "memory")

// ldmatrix x4 (bit-level 16B-row gather; valid for tf32 fragments)
__device__ __forceinline__ void ldsm_x4(uint32_t* r, uint32_t addr) {
    asm volatile("ldmatrix.sync.aligned.m8n8.x4.shared.b16 {%0,%1,%2,%3}, [%4];"
                 : "=r"(r[0]), "=r"(r[1]), "=r"(r[2]), "=r"(r[3]) : "r"(addr));
}

#define MMA_TF32(c, a, b)                                                     \
    asm volatile(                                                             \
        "mma.sync.aligned.m16n8k8.row.col.f32.tf32.tf32.f32 "                 \
        "{%0,%1,%2,%3}, {%4,%5,%6,%7}, {%8,%9}, {%0,%1,%2,%3};"               \
        : "+f"((c)[0]), "+f"((c)[1]), "+f"((c)[2]), "+f"((c)[3])              \
        : "r"((a)[0]), "r"((a)[1]), "r"((a)[2]), "r"((a)[3]),                 \
          "r"((b)[0]), "r"((b)[1]))

// ===========================================================================
// z -> tf32-rounded copy
// ===========================================================================
__global__ __launch_bounds__(256)
void round_copy_kernel(const float4* __restrict__ in, float4* __restrict__ out, int n4)
{
    int i = blockIdx.x * blockDim.x + threadIdx.x;
    if (i < n4) {
        float4 v = in[i];
        v.x = tf32r(v.x); v.y = tf32r(v.y);
        v.z = tf32r(v.z); v.w = tf32r(v.w);
        out[i] = v;
    }
}

// ===========================================================================
// Weight transpose + tf32 rounding
// ===========================================================================
__global__ __launch_bounds__(256)
void transpose_round_kernel(const float* __restrict__ W, float* __restrict__ WT,
                            int K, int N)
{
    __shared__ float tile[32][33];
    const int bx = blockIdx.x * 32;
    const int by = blockIdx.y * 32;
    const int tx = threadIdx.x;
    const int ty = threadIdx.y;
#pragma unroll
    for (int i = 0; i < 32; i += 8)
        tile[ty + i][tx] = W[(size_t)(by + ty + i) * N + bx + tx];
    __syncthreads();
#pragma unroll
    for (int i = 0; i < 32; i += 8)
        WT[(size_t)(bx + ty + i) * K + by + tx] = tf32r(tile[tx][ty + i]);
}

// ===========================================================================
// V transpose: vt[(n*16+h)*64 + d][t] = qkv[n*2048+t][2048 + h*64 + d]
// ===========================================================================
__global__ __launch_bounds__(256)
void vtrans_kernel(const float* __restrict__ qkv, float* __restrict__ vt)
{
    __shared__ float tile[32][33];
    const int nh = blockIdx.z;
    const int n = nh >> 4, h = nh & 15;
    const int t0 = blockIdx.x * 32;
    const int d0 = blockIdx.y * 32;
    const int tx = threadIdx.x;
    const int ty = threadIdx.y;
    const float* src = qkv + ((size_t)(n * TLEN + t0 + ty)) * QKVCOLS
                       + 2 * DMODEL + h * DK + d0 + tx;
#pragma unroll
    for (int i = 0; i < 32; i += 8)
        tile[ty + i][tx] = src[(size_t)i * QKVCOLS];
    __syncthreads();
    float* dst = vt + ((size_t)(nh * DK + d0 + ty)) * TLEN + t0 + tx;
#pragma unroll
    for (int i = 0; i < 32; i += 8)
        dst[(size_t)i * TLEN] = tile[tx][ty + i];
}

// ===========================================================================
// 3-stage pipelined tf32 GEMM with ldmatrix fragment loads.
// C[M,N] = A[M,K] * BT[N,K]^T; CTA 128x128, BK=32, 8 warps (2Mx4N).
// cp.async.wait_group 1: compute chunk it overlaps in-flight load of it+1.
// ===========================================================================
#define SSTRIDE 36
#define NSTAGE 3
#define GEMM_SMEM (NSTAGE * 2 * 128 * SSTRIDE * 4)   // 110.6 KB

__global__ __launch_bounds__(256, 2)
void tf32_gemm_pipe_kernel(const float* __restrict__ A, const float* __restrict__ BT,
                           float* __restrict__ C, int M, int N, int K,
                           int roundOut, int qlimit, float qscale)
{
    extern __shared__ float gs[];
    float* sA = gs;
    float* sB = gs + NSTAGE * 128 * SSTRIDE;

    const int tid = threadIdx.x;
    const int wid = tid >> 5;
    const int lane = tid & 31;
    const int row0 = blockIdx.y * 128;
    const int col0 = blockIdx.x * 128;

    const int warpM = wid >> 2;
    const int warpN = wid & 3;
    const int qrow = lane >> 2;
    const int qk   = lane & 3;

    const int lm_row = lane & 7;
    const int lm_mat = lane >> 3;
    const int rowA_off = lm_row + ((lm_mat & 1) << 3);
    const int colA_off = (lm_mat >> 1) << 2;
    const int rowB_off = lm_row;
    const int colB_off = lm_mat << 2;

    const int skq  = (tid & 7) << 2;
    const int srow = tid >> 3;

    const float* Abase = A  + (size_t)(row0 + srow) * K + skq;
    const float* Bbase = BT + (size_t)(col0 + srow) * K + skq;

    const uint32_t sA_u32 = smem_u32(sA);
    const uint32_t sB_u32 = smem_u32(sB);
    const uint32_t dA0 = sA_u32 + (uint32_t)(srow * SSTRIDE + skq) * 4u;
    const uint32_t dB0 = sB_u32 + (uint32_t)(srow * SSTRIDE + skq) * 4u;
    const uint32_t BUFB = 128u * SSTRIDE * 4u;

    const uint32_t aLm0 = sA_u32 +
        (uint32_t)((warpM * 64 + rowA_off) * SSTRIDE + colA_off) * 4u;
    const uint32_t bLm0 = sB_u32 +
        (uint32_t)((warpN * 32 + rowB_off) * SSTRIDE + colB_off) * 4u;

    float c[4][4][4];
#pragma unroll
    for (int mt = 0; mt < 4; mt++)
#pragma unroll
        for (int nt = 0; nt < 4; nt++)
#pragma unroll
            for (int r = 0; r < 4; r++) c[mt][nt][r] = 0.0f;

    const int niter = K >> 5;   // >= 2 for all our shapes

    // prologue: prefetch chunks 0,1 into stages 0,1
#pragma unroll
    for (int s = 0; s < 2; s++) {
        const int k0 = s << 5;
        const uint32_t bo = (uint32_t)s * BUFB;
#pragma unroll
        for (int i = 0; i < 4; i++) {
            cp16(dA0 + bo + (uint32_t)(i * 32 * SSTRIDE) * 4u,
                 Abase + (size_t)(i * 32) * K + k0);
            cp16(dB0 + bo + (uint32_t)(i * 32 * SSTRIDE) * 4u,
                 Bbase + (size_t)(i * 32) * K + k0);
        }
        CP_COMMIT();
    }

    int stage = 0;          // stage holding chunk `it`
    int pstage = 2;         // stage to prefetch into (chunk it+2)
    for (int it = 0; it < niter; it++) {
        CP_WAIT1();         // chunk `it` resident; `it+1` may still be in flight
        __syncthreads();

        if (it + 2 < niter) {
            const int k0 = (it + 2) << 5;
            const uint32_t bo = (uint32_t)pstage * BUFB;
#pragma unroll
            for (int i = 0; i < 4; i++) {
                cp16(dA0 + bo + (uint32_t)(i * 32 * SSTRIDE) * 4u,
                     Abase + (size_t)(i * 32) * K + k0);
                cp16(dB0 + bo + (uint32_t)(i * 32 * SSTRIDE) * 4u,
                     Bbase + (size_t)(i * 32) * K + k0);
            }
        }
        CP_COMMIT();        // always commit (empty groups keep the count uniform)

        const uint32_t bo = (uint32_t)stage * BUFB;
        const uint32_t aB = aLm0 + bo;
        const uint32_t bB = bLm0 + bo;

#pragma unroll
        for (int kh = 0; kh < 2; kh++) {
            uint32_t bfr[4][4];
#pragma unroll
            for (int nt = 0; nt < 4; nt++)
                ldsm_x4(bfr[nt], bB + (uint32_t)(nt * 8 * SSTRIDE + kh * 16) * 4u);
#pragma unroll
            for (int ks = 0; ks < 2; ks++) {
                const uint32_t kk = (uint32_t)(kh * 16 + ks * 8);
                uint32_t afr[4][4];
#pragma unroll
                for (int mt = 0; mt < 4; mt++)
                    ldsm_x4(afr[mt], aB + (uint32_t)(mt * 16 * SSTRIDE + kk) * 4u);
#pragma unroll
                for (int mt = 0; mt < 4; mt++)
#pragma unroll
                    for (int nt = 0; nt < 4; nt++)
                        MMA_TF32(c[mt][nt], afr[mt], &bfr[nt][2 * ks]);
            }
        }

        stage = (stage + 1 == NSTAGE) ? 0 : stage + 1;
        pstage = (pstage + 1 == NSTAGE) ? 0 : pstage + 1;
    }

    const float fac = (col0 < qlimit) ? qscale : 1.0f;
#pragma unroll
    for (int mt = 0; mt < 4; mt++) {
        const int r = row0 + warpM * 64 + mt * 16 + qrow;
#pragma unroll
        for (int nt = 0; nt < 4; nt++) {
            const int col = col0 + warpN * 32 + nt * 8 + qk * 2;
            float2 v0, v1;
            if (roundOut) {
                v0 = make_float2(tf32r(c[mt][nt][0] * fac), tf32r(c[mt][nt][1] * fac));
                v1 = make_float2(tf32r(c[mt][nt][2] * fac), tf32r(c[mt][nt][3] * fac));
            } else {
                v0 = make_float2(c[mt][nt][0], c[mt][nt][1]);
                v1 = make_float2(c[mt][nt][2], c[mt][nt][3]);
            }
            *reinterpret_cast<float2*>(C + (size_t)r * N + col) = v0;
            *reinterpret_cast<float2*>(C + (size_t)(r + 8) * N + col) = v1;
        }
    }
}

// ===========================================================================
// Tensor-core causal flash attention: ldmatrix fragments for K, P, V^T.
// (unchanged from round 6 — verified)
// ===========================================================================
#define KSTR 68
#define VSTR 68
#define PSTR 68
#define KBUF (64 * KSTR)
#define VBUF (64 * VSTR)
#define FLASH_SMEM ((2 * KBUF + 2 * VBUF + 128 * PSTR) * 4)

__global__ __launch_bounds__(256, 2)
void flash_attn_tc3_kernel(const float* __restrict__ qkv, const float* __restrict__ vt,
                           float* __restrict__ attout)
{
    extern __shared__ float smem[];
    float* sK = smem;
    float* sVT = smem + 2 * KBUF;
    float* sP = smem + 2 * KBUF + 2 * VBUF;

    const int qb = (int)gridDim.x - 1 - (int)blockIdx.x;
    const int h = blockIdx.y;
    const int n = blockIdx.z;
    const int tid = threadIdx.x;
    const int wid = tid >> 5;
    const int lane = tid & 31;
    const int qrow = lane >> 2;
    const int qk = lane & 3;
    const int q0 = qb * 128;

    const int lm_row = lane & 7;
    const int lm_mat = lane >> 3;
    const int rowA_off = lm_row + ((lm_mat & 1) << 3);
    const int colA_off = (lm_mat >> 1) << 2;
    const int rowB_off = lm_row;
    const int colB_off = lm_mat << 2;

    const size_t rs = QKVCOLS;
    const int ntiles = 2 * qb + 2;

    const int c4 = (tid & 15) << 2;
    const int r0 = tid >> 4;

    const float* kg0 = qkv + ((size_t)(n * TLEN) + r0) * rs + DMODEL + h * DK + c4;
    const float* vg0 = vt + ((size_t)((n * NH + h) * DK + r0)) * TLEN + c4;
    const uint32_t sK_u32 = smem_u32(sK);
    const uint32_t sVT_u32 = smem_u32(sVT);
    const uint32_t sP_u32 = smem_u32(sP);
    const uint32_t dK0 = sK_u32 + (uint32_t)(r0 * KSTR + c4) * 4u;
    const uint32_t dV0 = sVT_u32 + (uint32_t)(r0 * VSTR + c4) * 4u;

    {
#pragma unroll
        for (int r = 0; r < 4; r++) {
            cp16(dK0 + (uint32_t)(16 * r * KSTR) * 4u, kg0 + (size_t)(16 * r) * rs);
            cp16(dV0 + (uint32_t)(16 * r * VSTR) * 4u, vg0 + (size_t)(16 * r) * TLEN);
        }
        CP_COMMIT();
    }

    {
        const float* qg = qkv + ((size_t)(n * TLEN + q0 + r0)) * rs + h * DK + c4;
        float* ps = sP + r0 * PSTR + c4;
#pragma unroll
        for (int r = 0; r < 8; r++)
            *reinterpret_cast<float4*>(ps + 16 * r * PSTR) =
                *reinterpret_cast<const float4*>(qg + (size_t)(16 * r) * rs);
    }
    __syncthreads();

    uint32_t qf[8][4];
    {
        const uint32_t qLm = sP_u32 +
            (uint32_t)((wid * 16 + rowA_off) * PSTR + colA_off) * 4u;
#pragma unroll
        for (int kc = 0; kc < 8; kc++)
            ldsm_x4(qf[kc], qLm + (uint32_t)(kc * 8) * 4u);
    }

    float o[8][4];
#pragma unroll
    for (int nt = 0; nt < 8; nt++)
#pragma unroll
        for (int r = 0; r < 4; r++) o[nt][r] = 0.0f;

    float m0 = -1e30f, m1 = -1e30f, l0 = 0.0f, l1 = 0.0f;

    const int q_abs0 = q0 + wid * 16 + qrow;
    const int q_abs1 = q_abs0 + 8;
    const int wmax_kt = (q0 + wid * 16 + 15) >> 6;

    const uint32_t kLm0 = sK_u32 + (uint32_t)(rowB_off * KSTR + colB_off) * 4u;
    const uint32_t vLm0 = sVT_u32 + (uint32_t)(rowB_off * VSTR + colB_off) * 4u;
    const uint32_t pLm0 = sP_u32 +
        (uint32_t)((wid * 16 + rowA_off) * PSTR + colA_off) * 4u;

    for (int kt = 0; kt < ntiles; kt++) {
        CP_WAIT0();
        __syncthreads();

        if (kt + 1 < ntiles) {
            const uint32_t bK = ((kt + 1) & 1) * (uint32_t)(KBUF * 4);
            const uint32_t bV = ((kt + 1) & 1) * (uint32_t)(VBUF * 4);
            const float* kg = kg0 + (size_t)((kt + 1) * 64) * rs;
            const float* vg = vg0 + (kt + 1) * 64;
#pragma unroll
            for (int r = 0; r < 4; r++) {
                cp16(dK0 + bK + (uint32_t)(16 * r * KSTR) * 4u, kg + (size_t)(16 * r) * rs);
                cp16(dV0 + bV + (uint32_t)(16 * r * VSTR) * 4u, vg + (size_t)(16 * r) * TLEN);
            }
            CP_COMMIT();
        }

        if (kt > wmax_kt) continue;

        const uint32_t kB = kLm0 + (kt & 1) * (uint32_t)(KBUF * 4);
        const uint32_t vB = vLm0 + (kt & 1) * (uint32_t)(VBUF * 4);

        float s[8][4];
#pragma unroll
        for (int nt = 0; nt < 8; nt++)
#pragma unroll
            for (int r = 0; r < 4; r++) s[nt][r] = 0.0f;

#pragma unroll
        for (int kcp = 0; kcp < 4; kcp++) {
#pragma unroll
            for (int nt = 0; nt < 8; nt++) {
                uint32_t bk[4];
                ldsm_x4(bk, kB + (uint32_t)(nt * 8 * KSTR + kcp * 16) * 4u);
                MMA_TF32(s[nt], qf[2 * kcp], &bk[0]);
                MMA_TF32(s[nt], qf[2 * kcp + 1], &bk[2]);
            }
        }

        if (((kt << 6) + 63) > (q0 + wid * 16)) {
#pragma unroll
            for (int nt = 0; nt < 8; nt++) {
                const int c0 = (kt << 6) + (nt << 3) + (qk << 1);
                if (c0     > q_abs0) s[nt][0] = -1e30f;
                if (c0 + 1 > q_abs0) s[nt][1] = -1e30f;
                if (c0     > q_abs1) s[nt][2] = -1e30f;
                if (c0 + 1 > q_abs1) s[nt][3] = -1e30f;
            }
        }

        float rm0 = -1e30f, rm1 = -1e30f;
#pragma unroll
        for (int nt = 0; nt < 8; nt++) {
            rm0 = fmaxf(rm0, fmaxf(s[nt][0], s[nt][1]));
            rm1 = fmaxf(rm1, fmaxf(s[nt][2], s[nt][3]));
        }
        rm0 = fmaxf(rm0, __shfl_xor_sync(0xffffffffu, rm0, 1));
        rm0 = fmaxf(rm0, __shfl_xor_sync(0xffffffffu, rm0, 2));
        rm1 = fmaxf(rm1, __shfl_xor_sync(0xffffffffu, rm1, 1));
        rm1 = fmaxf(rm1, __shfl_xor_sync(0xffffffffu, rm1, 2));

        const float mn0 = fmaxf(m0, rm0);
        const float mn1 = fmaxf(m1, rm1);
        const float corr0 = ex2(m0 - mn0);
        const float corr1 = ex2(m1 - mn1);
        m0 = mn0; m1 = mn1;

        float rs0 = 0.0f, rs1 = 0.0f;
#pragma unroll
        for (int nt = 0; nt < 8; nt++) {
            s[nt][0] = ex2(s[nt][0] - mn0);
            s[nt][1] = ex2(s[nt][1] - mn0);
            s[nt][2] = ex2(s[nt][2] - mn1);
            s[nt][3] = ex2(s[nt][3] - mn1);
            rs0 += s[nt][0] + s[nt][1];
            rs1 += s[nt][2] + s[nt][3];
        }
        rs0 += __shfl_xor_sync(0xffffffffu, rs0, 1);
        rs0 += __shfl_xor_sync(0xffffffffu, rs0, 2);
        rs1 += __shfl_xor_sync(0xffffffffu, rs1, 1);
        rs1 += __shfl_xor_sync(0xffffffffu, rs1, 2);

        l0 = l0 * corr0 + rs0;
        l1 = l1 * corr1 + rs1;

#pragma unroll
        for (int nt = 0; nt < 8; nt++) {
            o[nt][0] *= corr0; o[nt][1] *= corr0;
            o[nt][2] *= corr1; o[nt][3] *= corr1;
        }

        {
            float* pw = sP + (wid * 16 + qrow) * PSTR + (qk << 1);
#pragma unroll
            for (int nt = 0; nt < 8; nt++) {
                *reinterpret_cast<float2*>(pw + nt * 8) =
                    make_float2(tf32r(s[nt][0]), tf32r(s[nt][1]));
                *reinterpret_cast<float2*>(pw + 8 * PSTR + nt * 8) =
                    make_float2(tf32r(s[nt][2]), tf32r(s[nt][3]));
            }
        }
        __syncwarp();

#pragma unroll
        for (int kvp = 0; kvp < 4; kvp++) {
            uint32_t af0[4], af1[4];
            ldsm_x4(af0, pLm0 + (uint32_t)(kvp * 16) * 4u);
            ldsm_x4(af1, pLm0 + (uint32_t)(kvp * 16 + 8) * 4u);
#pragma unroll
            for (int nt = 0; nt < 8; nt++) {
                uint32_t bv[4];
                ldsm_x4(bv, vB + (uint32_t)(nt * 8 * VSTR + kvp * 16) * 4u);
                MMA_TF32(o[nt], af0, &bv[0]);
                MMA_TF32(o[nt], af1, &bv[2]);
            }
        }
        __syncwarp();
    }

    const float inv0 = 1.0f / l0;
    const float inv1 = 1.0f / l1;
    float* ob = attout + ((size_t)(n * TLEN + q0 + wid * 16 + qrow)) * DMODEL
                + h * DK + (qk << 1);
#pragma unroll
    for (int nt = 0; nt < 8; nt++) {
        *reinterpret_cast<float2*>(ob + nt * 8) =
            make_float2(tf32r(o[nt][0] * inv0), tf32r(o[nt][1] * inv0));
        *reinterpret_cast<float2*>(ob + (size_t)8 * DMODEL + nt * 8) =
            make_float2(tf32r(o[nt][2] * inv1), tf32r(o[nt][3] * inv1));
    }
}

// ---------------------------------------------------------------------------
// Launch
// ---------------------------------------------------------------------------
extern "C" void kernel_launch(void* const* d_in, const int* in_sizes, int n_in,
                              void* d_out, int out_size)
{
    const float* z    = (const float*)d_in[0];
    const float* Wqkv = (const float*)d_in[1];
    const float* Wout = (const float*)d_in[2];
    float* out = (float*)d_out;

    void *pqkv, *patt, *pzr, *pvt, *pwq, *pwo;
    cudaGetSymbolAddress(&pqkv, g_qkv);
    cudaGetSymbolAddress(&patt, g_att);
    cudaGetSymbolAddress(&pzr, g_zr);
    cudaGetSymbolAddress(&pvt, g_vt);
    cudaGetSymbolAddress(&pwq, g_wtqkv);
    cudaGetSymbolAddress(&pwo, g_wtout);
    float* qkv = (float*)pqkv;
    float* att = (float*)patt;
    float* zr  = (float*)pzr;
    float* vt  = (float*)pvt;
    float* wtq = (float*)pwq;
    float* wto = (float*)pwo;

    cudaFuncSetAttribute(tf32_gemm_pipe_kernel,
                         cudaFuncAttributeMaxDynamicSharedMemorySize, GEMM_SMEM);
    cudaFuncSetAttribute(flash_attn_tc3_kernel,
                         cudaFuncAttributeMaxDynamicSharedMemorySize, FLASH_SMEM);

    {
        const int n4 = MROWS * DMODEL / 4;
        round_copy_kernel<<<(n4 + 255) / 256, 256>>>(
            (const float4*)z, (float4*)zr, n4);
    }
    transpose_round_kernel<<<dim3(QKVCOLS / 32, DMODEL / 32), dim3(32, 8)>>>(
        Wqkv, wtq, DMODEL, QKVCOLS);
    transpose_round_kernel<<<dim3(DMODEL / 32, DMODEL / 32), dim3(32, 8)>>>(
        Wout, wto, DMODEL, DMODEL);

    tf32_gemm_pipe_kernel<<<dim3(QKVCOLS / 128, MROWS / 128), 256, GEMM_SMEM>>>(
        zr, wtq, qkv, MROWS, QKVCOLS, DMODEL, 1, DMODEL, QSCALE);

    vtrans_kernel<<<dim3(TLEN / 32, DK / 32, NB * NH), dim3(32, 8)>>>(qkv, vt);

    flash_attn_tc3_kernel<<<dim3(TLEN / 128, NH, NB), 256, FLASH_SMEM>>>(qkv, vt, att);

    tf32_gemm_pipe_kernel<<<dim3(DMODEL / 128, MROWS / 128), 256, GEMM_SMEM>>>(
        att, wto, out, MROWS, DMODEL, DMODEL, 0, 0, 1.0f);
}

// round 8
// speedup vs baseline: 1.7486x; 1.7486x over previous
#include <cuda_runtime.h>
#include <cuda_fp16.h>
#include <cstdint>
#include <cstddef>

// Problem constants
#define NB   4
#define TLEN 2048
#define DMODEL 1024
#define NH   16
#define DK   64
#define MROWS (NB * TLEN)        // 8192
#define QKVCOLS (3 * DMODEL)     // 3072

// Q pre-scale: 1/sqrt(64) * log2(e)  (softmax runs in exp2 domain)
#define QSCALE 0.1803368801111204f

// Scratch (device globals) — fp16 datapath
__device__ __half g_qkv[(size_t)MROWS * QKVCOLS];       // 50.3 MB (Q pre-scaled)
__device__ __half g_att[(size_t)MROWS * DMODEL];        // 16.8 MB
__device__ __half g_zr[(size_t)MROWS * DMODEL];         // 16.8 MB
__device__ __half g_vt[(size_t)NB * NH * DK * TLEN];    // 16.8 MB (V^T per (n,h): [d][t])
__device__ __half g_wtqkv[(size_t)QKVCOLS * DMODEL];    // 6.3 MB
__device__ __half g_wtout[(size_t)DMODEL * DMODEL];     // 2.1 MB

__device__ __forceinline__ float ex2(float x) {
    float y;
    asm("ex2.approx.f32 %0, %1;" : "=f"(y) : "f"(x));
    return y;
}

__device__ __forceinline__ uint32_t smem_u32(const void* p) {
    uint32_t a;
    asm("{ .reg .u64 t; cvta.to.shared.u64 t, %1; cvt.u32.u64 %0, t; }"
        : "=r"(a) : "l"(p));
    return a;
}

__device__ __forceinline__ void cp16(uint32_t dst, const void* src) {
    asm volatile("cp.async.cg.shared.global [%0], [%1], 16;"
                 :: "r"(dst), "l"(src));
}
#define CP_COMMIT() asm volatile("cp.async.commit_group;" ::: "memory")
#define CP_WAIT0()  asm volatile("cp.async.wait_group 0;" ::: "memory")
#define CP_WAIT1()  asm volatile("cp.async.wait_group 1;" ::: "memory")

__device__ __forceinline__ void ldsm_x4(uint32_t* r, uint32_t addr) {
    asm volatile("ldmatrix.sync.aligned.m8n8.x4.shared.b16 {%0,%1,%2,%3}, [%4];"
                 : "=r"(r[0]), "=r"(r[1]), "=r"(r[2]), "=r"(r[3]) : "r"(addr));
}

#define MMA_F16(c, a, b)                                                      \
    asm volatile(                                                             \
        "mma.sync.aligned.m16n8k16.row.col.f32.f16.f16.f32 "                  \
        "{%0,%1,%2,%3}, {%4,%5,%6,%7}, {%8,%9}, {%0,%1,%2,%3};"               \
        : "+f"((c)[0]), "+f"((c)[1]), "+f"((c)[2]), "+f"((c)[3])              \
        : "r"((a)[0]), "r"((a)[1]), "r"((a)[2]), "r"((a)[3]),                 \
          "r"((b)[0]), "r"((b)[1]))

// ===========================================================================
// z (fp32) -> fp16 copy
// ===========================================================================
__global__ __launch_bounds__(256)
void round_copy_kernel(const float4* __restrict__ in, __half2* __restrict__ out, int n4)
{
    int i = blockIdx.x * blockDim.x + threadIdx.x;
    if (i < n4) {
        float4 v = in[i];
        out[2 * i]     = __floats2half2_rn(v.x, v.y);
        out[2 * i + 1] = __floats2half2_rn(v.z, v.w);
    }
}

// ===========================================================================
// Weight transpose + fp16: WT[n][k] = h(W[k][n]); W is [K,N] fp32 row-major.
// ===========================================================================
__global__ __launch_bounds__(256)
void transpose_round_kernel(const float* __restrict__ W, __half* __restrict__ WT,
                            int K, int N)
{
    __shared__ float tile[32][33];
    const int bx = blockIdx.x * 32;
    const int by = blockIdx.y * 32;
    const int tx = threadIdx.x;
    const int ty = threadIdx.y;
#pragma unroll
    for (int i = 0; i < 32; i += 8)
        tile[ty + i][tx] = W[(size_t)(by + ty + i) * N + bx + tx];
    __syncthreads();
#pragma unroll
    for (int i = 0; i < 32; i += 8)
        WT[(size_t)(bx + ty + i) * K + by + tx] = __float2half_rn(tile[tx][ty + i]);
}

// ===========================================================================
// V transpose (fp16): vt[(n*16+h)*64 + d][t] = qkv[n*2048+t][2048 + h*64 + d]
// ===========================================================================
__global__ __launch_bounds__(256)
void vtrans_kernel(const __half* __restrict__ qkv, __half* __restrict__ vt)
{
    __shared__ __half tile[32][33];
    const int nh = blockIdx.z;
    const int n = nh >> 4, h = nh & 15;
    const int t0 = blockIdx.x * 32;
    const int d0 = blockIdx.y * 32;
    const int tx = threadIdx.x;
    const int ty = threadIdx.y;
    const __half* src = qkv + ((size_t)(n * TLEN + t0 + ty)) * QKVCOLS
                        + 2 * DMODEL + h * DK + d0 + tx;
#pragma unroll
    for (int i = 0; i < 32; i += 8)
        tile[ty + i][tx] = src[(size_t)i * QKVCOLS];
    __syncthreads();
    __half* dst = vt + ((size_t)(nh * DK + d0 + ty)) * TLEN + t0 + tx;
#pragma unroll
    for (int i = 0; i < 32; i += 8)
        dst[(size_t)i * TLEN] = tile[tx][ty + i];
}

// ===========================================================================
// 3-stage pipelined fp16 GEMM: C[M,N] = A[M,K] * BT[N,K]^T.
// CTA 128x128, BK=32 halves, 8 warps (2Mx4N), m16n8k16, f32 accumulate.
// OUT_HALF=1: C is __half (scaled by qscale for cols < qlimit); else fp32.
// ===========================================================================
#define ASTR 40               // halves; 20 words -> conflict-free ldmatrix rows
#define NSTAGE 3
#define GEMM_SMEM (NSTAGE * 2 * 128 * ASTR * 2)   // 61440 B

template <int OUT_HALF>
__global__ __launch_bounds__(256, 2)
void f16_gemm_kernel(const __half* __restrict__ A, const __half* __restrict__ BT,
                     void* __restrict__ Cout, int M, int N, int K,
                     int qlimit, float qscale)
{
    extern __shared__ __half hs[];
    __half* sA = hs;
    __half* sB = hs + NSTAGE * 128 * ASTR;

    const int tid = threadIdx.x;
    const int wid = tid >> 5;
    const int lane = tid & 31;
    const int row0 = blockIdx.y * 128;
    const int col0 = blockIdx.x * 128;

    const int warpM = wid >> 2;
    const int warpN = wid & 3;
    const int qrow = lane >> 2;
    const int qk   = lane & 3;

    const int lm_row = lane & 7;
    const int lm_mat = lane >> 3;
    const int rowA_off = lm_row + ((lm_mat & 1) << 3);
    const int colA_off = (lm_mat >> 1) << 3;          // halves (0 or 8)
    const int colB_off = lm_mat << 3;                 // halves (0,8,16,24)

    // staging: 512 16B-chunks per operand; chunk c: row=c>>2, part=(c&3)*8 halves
    int srow[2], spart[2];
#pragma unroll
    for (int i = 0; i < 2; i++) {
        const int c = tid + (i << 8);
        srow[i] = c >> 2;
        spart[i] = (c & 3) << 3;
    }

    const uint32_t sA_u32 = smem_u32(sA);
    const uint32_t sB_u32 = smem_u32(sB);
    const uint32_t BUFB = 128u * ASTR * 2u;           // bytes per stage

    const __half* Ab[2];
    const __half* Bb[2];
    uint32_t dA[2], dB[2];
#pragma unroll
    for (int i = 0; i < 2; i++) {
        Ab[i] = A  + (size_t)(row0 + srow[i]) * K + spart[i];
        Bb[i] = BT + (size_t)(col0 + srow[i]) * K + spart[i];
        dA[i] = sA_u32 + (uint32_t)(srow[i] * ASTR + spart[i]) * 2u;
        dB[i] = sB_u32 + (uint32_t)(srow[i] * ASTR + spart[i]) * 2u;
    }

    const uint32_t aLm0 = sA_u32 +
        (uint32_t)((warpM * 64 + rowA_off) * ASTR + colA_off) * 2u;
    const uint32_t bLm0 = sB_u32 +
        (uint32_t)((warpN * 32 + lm_row) * ASTR + colB_off) * 2u;

    float c[4][4][4];
#pragma unroll
    for (int mt = 0; mt < 4; mt++)
#pragma unroll
        for (int nt = 0; nt < 4; nt++)
#pragma unroll
            for (int r = 0; r < 4; r++) c[mt][nt][r] = 0.0f;

    const int niter = K >> 5;

    // prologue: prefetch chunks 0,1
#pragma unroll
    for (int s = 0; s < 2; s++) {
        const int k0 = s << 5;
        const uint32_t bo = (uint32_t)s * BUFB;
#pragma unroll
        for (int i = 0; i < 2; i++) {
            cp16(dA[i] + bo, Ab[i] + k0);
            cp16(dB[i] + bo, Bb[i] + k0);
        }
        CP_COMMIT();
    }

    int stage = 0, pstage = 2;
    for (int it = 0; it < niter; it++) {
        CP_WAIT1();
        __syncthreads();

        if (it + 2 < niter) {
            const int k0 = (it + 2) << 5;
            const uint32_t bo = (uint32_t)pstage * BUFB;
#pragma unroll
            for (int i = 0; i < 2; i++) {
                cp16(dA[i] + bo, Ab[i] + k0);
                cp16(dB[i] + bo, Bb[i] + k0);
            }
        }
        CP_COMMIT();

        const uint32_t bo = (uint32_t)stage * BUFB;
        const uint32_t aB = aLm0 + bo;
        const uint32_t bB = bLm0 + bo;

        uint32_t bfr[4][4];
#pragma unroll
        for (int nt = 0; nt < 4; nt++)
            ldsm_x4(bfr[nt], bB + (uint32_t)(nt * 8 * ASTR) * 2u);   // k 0..31

#pragma unroll
        for (int kh = 0; kh < 2; kh++) {          // k-chunks of 16
            uint32_t afr[4][4];
#pragma unroll
            for (int mt = 0; mt < 4; mt++)
                ldsm_x4(afr[mt], aB + (uint32_t)(mt * 16 * ASTR + kh * 16) * 2u);
#pragma unroll
            for (int mt = 0; mt < 4; mt++)
#pragma unroll
                for (int nt = 0; nt < 4; nt++)
                    MMA_F16(c[mt][nt], afr[mt], &bfr[nt][2 * kh]);
        }

        stage = (stage + 1 == NSTAGE) ? 0 : stage + 1;
        pstage = (pstage + 1 == NSTAGE) ? 0 : pstage + 1;
    }

    const float fac = (col0 < qlimit) ? qscale : 1.0f;
#pragma unroll
    for (int mt = 0; mt < 4; mt++) {
        const int r = row0 + warpM * 64 + mt * 16 + qrow;
#pragma unroll
        for (int nt = 0; nt < 4; nt++) {
            const int col = col0 + warpN * 32 + nt * 8 + qk * 2;
            if (OUT_HALF) {
                __half* Ch = (__half*)Cout;
                *reinterpret_cast<__half2*>(Ch + (size_t)r * N + col) =
                    __floats2half2_rn(c[mt][nt][0] * fac, c[mt][nt][1] * fac);
                *reinterpret_cast<__half2*>(Ch + (size_t)(r + 8) * N + col) =
                    __floats2half2_rn(c[mt][nt][2] * fac, c[mt][nt][3] * fac);
            } else {
                float* Cf = (float*)Cout;
                *reinterpret_cast<float2*>(Cf + (size_t)r * N + col) =
                    make_float2(c[mt][nt][0], c[mt][nt][1]);
                *reinterpret_cast<float2*>(Cf + (size_t)(r + 8) * N + col) =
                    make_float2(c[mt][nt][2], c[mt][nt][3]);
            }
        }
    }
}

// ===========================================================================
// fp16 tensor-core causal flash attention. m16n8k16, f32 accum/softmax.
// CTA: 128 q-rows; 8 warps, 16 q-rows each; 64-wide kv tiles double-buffered.
// ===========================================================================
#define KSTR 72               // halves; 36 words -> conflict-free
#define PSTR 72
#define KBUF (64 * KSTR)      // halves per stage
#define FLASH_SMEM ((2 * KBUF + 2 * KBUF + 128 * PSTR) * 2)

__global__ __launch_bounds__(256, 2)
void flash_attn_f16_kernel(const __half* __restrict__ qkv, const __half* __restrict__ vt,
                           __half* __restrict__ attout)
{
    extern __shared__ __half smem[];
    __half* sK = smem;                       // [2][64][KSTR] rows = key t
    __half* sVT = smem + 2 * KBUF;           // [2][64][KSTR] rows = d
    __half* sP = smem + 4 * KBUF;            // [128][PSTR]

    const int qb = (int)gridDim.x - 1 - (int)blockIdx.x;
    const int h = blockIdx.y;
    const int n = blockIdx.z;
    const int tid = threadIdx.x;
    const int wid = tid >> 5;
    const int lane = tid & 31;
    const int qrow = lane >> 2;
    const int qk = lane & 3;
    const int q0 = qb * 128;

    const int lm_row = lane & 7;
    const int lm_mat = lane >> 3;
    const int rowA_off = lm_row + ((lm_mat & 1) << 3);
    const int colA_off = (lm_mat >> 1) << 3;
    const int colB_off = lm_mat << 3;

    const size_t rs = QKVCOLS;
    const int ntiles = 2 * qb + 2;

    // K/V staging: 512 chunks; c: row=c>>3, part=(c&7)*8 halves
    int krow[2], kpart[2];
#pragma unroll
    for (int i = 0; i < 2; i++) {
        const int c = tid + (i << 8);
        krow[i] = c >> 3;
        kpart[i] = (c & 7) << 3;
    }

    const uint32_t sK_u32 = smem_u32(sK);
    const uint32_t sVT_u32 = smem_u32(sVT);
    const uint32_t sP_u32 = smem_u32(sP);

    const __half* kg[2];
    const __half* vg[2];
    uint32_t dK[2], dV[2];
#pragma unroll
    for (int i = 0; i < 2; i++) {
        kg[i] = qkv + ((size_t)(n * TLEN) + krow[i]) * rs + DMODEL + h * DK + kpart[i];
        vg[i] = vt + ((size_t)((n * NH + h) * DK + krow[i])) * TLEN + kpart[i];
        dK[i] = sK_u32 + (uint32_t)(krow[i] * KSTR + kpart[i]) * 2u;
        dV[i] = sVT_u32 + (uint32_t)(krow[i] * KSTR + kpart[i]) * 2u;
    }

    // prefetch K/V tile 0
    {
#pragma unroll
        for (int i = 0; i < 2; i++) {
            cp16(dK[i], kg[i]);
            cp16(dV[i], vg[i]);
        }
        CP_COMMIT();
    }

    // stage Q: 128 rows x 64 halves, 1024 chunks
    {
#pragma unroll
        for (int i = 0; i < 4; i++) {
            const int cq = tid + (i << 8);
            const int row = cq >> 3, part = (cq & 7) << 3;
            const __half* qg = qkv + ((size_t)(n * TLEN + q0 + row)) * rs + h * DK + part;
            *reinterpret_cast<uint4*>(sP + row * PSTR + part) =
                *reinterpret_cast<const uint4*>(qg);
        }
    }
    __syncthreads();

    // Q fragments: d split into 4 chunks of 16
    uint32_t qf[4][4];
    {
        const uint32_t qLm = sP_u32 +
            (uint32_t)((wid * 16 + rowA_off) * PSTR + colA_off) * 2u;
#pragma unroll
        for (int kc = 0; kc < 4; kc++)
            ldsm_x4(qf[kc], qLm + (uint32_t)(kc * 16) * 2u);
    }

    float o[8][4];
#pragma unroll
    for (int nt = 0; nt < 8; nt++)
#pragma unroll
        for (int r = 0; r < 4; r++) o[nt][r] = 0.0f;

    float m0 = -1e30f, m1 = -1e30f, l0 = 0.0f, l1 = 0.0f;

    const int q_abs0 = q0 + wid * 16 + qrow;
    const int q_abs1 = q_abs0 + 8;
    const int wmax_kt = (q0 + wid * 16 + 15) >> 6;

    const uint32_t kLm0 = sK_u32 + (uint32_t)(lm_row * KSTR + colB_off) * 2u;
    const uint32_t vLm0 = sVT_u32 + (uint32_t)(lm_row * KSTR + colB_off) * 2u;
    const uint32_t pLm0 = sP_u32 +
        (uint32_t)((wid * 16 + rowA_off) * PSTR + colA_off) * 2u;

    for (int kt = 0; kt < ntiles; kt++) {
        CP_WAIT0();
        __syncthreads();

        if (kt + 1 < ntiles) {
            const uint32_t bo = ((kt + 1) & 1) * (uint32_t)(KBUF * 2);
#pragma unroll
            for (int i = 0; i < 2; i++) {
                cp16(dK[i] + bo, kg[i] + (size_t)((kt + 1) * 64) * rs);
                cp16(dV[i] + bo, vg[i] + (kt + 1) * 64);
            }
            CP_COMMIT();
        }

        if (kt > wmax_kt) continue;

        const uint32_t kB = kLm0 + (kt & 1) * (uint32_t)(KBUF * 2);
        const uint32_t vB = vLm0 + (kt & 1) * (uint32_t)(KBUF * 2);

        // ---- S = Q K^T ----
        float s[8][4];
#pragma unroll
        for (int nt = 0; nt < 8; nt++)
#pragma unroll
            for (int r = 0; r < 4; r++) s[nt][r] = 0.0f;

#pragma unroll
        for (int nt = 0; nt < 8; nt++) {
            uint32_t bk[8];
            ldsm_x4(&bk[0], kB + (uint32_t)(nt * 8 * KSTR) * 2u);        // d 0..31
            ldsm_x4(&bk[4], kB + (uint32_t)(nt * 8 * KSTR + 32) * 2u);   // d 32..63
            MMA_F16(s[nt], qf[0], &bk[0]);
            MMA_F16(s[nt], qf[1], &bk[2]);
            MMA_F16(s[nt], qf[2], &bk[4]);
            MMA_F16(s[nt], qf[3], &bk[6]);
        }

        // ---- causal mask ----
        if (((kt << 6) + 63) > (q0 + wid * 16)) {
#pragma unroll
            for (int nt = 0; nt < 8; nt++) {
                const int c0 = (kt << 6) + (nt << 3) + (qk << 1);
                if (c0     > q_abs0) s[nt][0] = -1e30f;
                if (c0 + 1 > q_abs0) s[nt][1] = -1e30f;
                if (c0     > q_abs1) s[nt][2] = -1e30f;
                if (c0 + 1 > q_abs1) s[nt][3] = -1e30f;
            }
        }

        // ---- online softmax (exp2 domain) ----
        float rm0 = -1e30f, rm1 = -1e30f;
#pragma unroll
        for (int nt = 0; nt < 8; nt++) {
            rm0 = fmaxf(rm0, fmaxf(s[nt][0], s[nt][1]));
            rm1 = fmaxf(rm1, fmaxf(s[nt][2], s[nt][3]));
        }
        rm0 = fmaxf(rm0, __shfl_xor_sync(0xffffffffu, rm0, 1));
        rm0 = fmaxf(rm0, __shfl_xor_sync(0xffffffffu, rm0, 2));
        rm1 = fmaxf(rm1, __shfl_xor_sync(0xffffffffu, rm1, 1));
        rm1 = fmaxf(rm1, __shfl_xor_sync(0xffffffffu, rm1, 2));

        const float mn0 = fmaxf(m0, rm0);
        const float mn1 = fmaxf(m1, rm1);
        const float corr0 = ex2(m0 - mn0);
        const float corr1 = ex2(m1 - mn1);
        m0 = mn0; m1 = mn1;

        float rs0 = 0.0f, rs1 = 0.0f;
#pragma unroll
        for (int nt = 0; nt < 8; nt++) {
            s[nt][0] = ex2(s[nt][0] - mn0);
            s[nt][1] = ex2(s[nt][1] - mn0);
            s[nt][2] = ex2(s[nt][2] - mn1);
            s[nt][3] = ex2(s[nt][3] - mn1);
            rs0 += s[nt][0] + s[nt][1];
            rs1 += s[nt][2] + s[nt][3];
        }
        rs0 += __shfl_xor_sync(0xffffffffu, rs0, 1);
        rs0 += __shfl_xor_sync(0xffffffffu, rs0, 2);
        rs1 += __shfl_xor_sync(0xffffffffu, rs1, 1);
        rs1 += __shfl_xor_sync(0xffffffffu, rs1, 2);

        l0 = l0 * corr0 + rs0;
        l1 = l1 * corr1 + rs1;

#pragma unroll
        for (int nt = 0; nt < 8; nt++) {
            o[nt][0] *= corr0; o[nt][1] *= corr0;
            o[nt][2] *= corr1; o[nt][3] *= corr1;
        }

        // ---- P -> smem (warp-private rows), fp16 ----
        {
            __half* pw = sP + (wid * 16 + qrow) * PSTR + (qk << 1);
#pragma unroll
            for (int nt = 0; nt < 8; nt++) {
                *reinterpret_cast<__half2*>(pw + nt * 8) =
                    __floats2half2_rn(s[nt][0], s[nt][1]);
                *reinterpret_cast<__half2*>(pw + 8 * PSTR + nt * 8) =
                    __floats2half2_rn(s[nt][2], s[nt][3]);
            }
        }
        __syncwarp();

        // ---- O += P V ----
        uint32_t afP[4][4];
#pragma unroll
        for (int kvp = 0; kvp < 4; kvp++)
            ldsm_x4(afP[kvp], pLm0 + (uint32_t)(kvp * 16) * 2u);
#pragma unroll
        for (int nt = 0; nt < 8; nt++) {
            uint32_t bv[8];
            ldsm_x4(&bv[0], vB + (uint32_t)(nt * 8 * KSTR) * 2u);        // t 0..31
            ldsm_x4(&bv[4], vB + (uint32_t)(nt * 8 * KSTR + 32) * 2u);   // t 32..63
            MMA_F16(o[nt], afP[0], &bv[0]);
            MMA_F16(o[nt], afP[1], &bv[2]);
            MMA_F16(o[nt], afP[2], &bv[4]);
            MMA_F16(o[nt], afP[3], &bv[6]);
        }
        __syncwarp();
    }

    // ---- epilogue: normalize, fp16 store ----
    const float inv0 = 1.0f / l0;
    const float inv1 = 1.0f / l1;
    __half* ob = attout + ((size_t)(n * TLEN + q0 + wid * 16 + qrow)) * DMODEL
                 + h * DK + (qk << 1);
#pragma unroll
    for (int nt = 0; nt < 8; nt++) {
        *reinterpret_cast<__half2*>(ob + nt * 8) =
            __floats2half2_rn(o[nt][0] * inv0, o[nt][1] * inv0);
        *reinterpret_cast<__half2*>(ob + (size_t)8 * DMODEL + nt * 8) =
            __floats2half2_rn(o[nt][2] * inv1, o[nt][3] * inv1);
    }
}

// ---------------------------------------------------------------------------
// Launch
// ---------------------------------------------------------------------------
extern "C" void kernel_launch(void* const* d_in, const int* in_sizes, int n_in,
                              void* d_out, int out_size)
{
    const float* z    = (const float*)d_in[0];
    const float* Wqkv = (const float*)d_in[1];
    const float* Wout = (const float*)d_in[2];
    float* out = (float*)d_out;

    void *pqkv, *patt, *pzr, *pvt, *pwq, *pwo;
    cudaGetSymbolAddress(&pqkv, g_qkv);
    cudaGetSymbolAddress(&patt, g_att);
    cudaGetSymbolAddress(&pzr, g_zr);
    cudaGetSymbolAddress(&pvt, g_vt);
    cudaGetSymbolAddress(&pwq, g_wtqkv);
    cudaGetSymbolAddress(&pwo, g_wtout);
    __half* qkv = (__half*)pqkv;
    __half* att = (__half*)patt;
    __half* zr  = (__half*)pzr;
    __half* vt  = (__half*)pvt;
    __half* wtq = (__half*)pwq;
    __half* wto = (__half*)pwo;

    cudaFuncSetAttribute(f16_gemm_kernel<1>,
                         cudaFuncAttributeMaxDynamicSharedMemorySize, GEMM_SMEM);
    cudaFuncSetAttribute(f16_gemm_kernel<0>,
                         cudaFuncAttributeMaxDynamicSharedMemorySize, GEMM_SMEM);
    cudaFuncSetAttribute(flash_attn_f16_kernel,
                         cudaFuncAttributeMaxDynamicSharedMemorySize, FLASH_SMEM);

    // 0) z -> fp16; weights transpose -> fp16
    {
        const int n4 = MROWS * DMODEL / 4;
        round_copy_kernel<<<(n4 + 255) / 256, 256>>>(
            (const float4*)z, (__half2*)zr, n4);
    }
    transpose_round_kernel<<<dim3(QKVCOLS / 32, DMODEL / 32), dim3(32, 8)>>>(
        Wqkv, wtq, DMODEL, QKVCOLS);
    transpose_round_kernel<<<dim3(DMODEL / 32, DMODEL / 32), dim3(32, 8)>>>(
        Wout, wto, DMODEL, DMODEL);

    // 1) qkv = z @ Wqkv  (fp16 out; Q cols pre-scaled by QSCALE)
    f16_gemm_kernel<1><<<dim3(QKVCOLS / 128, MROWS / 128), 256, GEMM_SMEM>>>(
        zr, wtq, (void*)qkv, MROWS, QKVCOLS, DMODEL, DMODEL, QSCALE);

    // 1b) V^T per (n,h)
    vtrans_kernel<<<dim3(TLEN / 32, DK / 32, NB * NH), dim3(32, 8)>>>(qkv, vt);

    // 2) causal flash attention (fp16 tensor cores)
    flash_attn_f16_kernel<<<dim3(TLEN / 128, NH, NB), 256, FLASH_SMEM>>>(qkv, vt, att);

    // 3) out = att @ Wout  (fp32 out)
    f16_gemm_kernel<0><<<dim3(DMODEL / 128, MROWS / 128), 256, GEMM_SMEM>>>(
        att, wto, (void*)out, MROWS, DMODEL, DMODEL, 0, 1.0f);
}